// round 11
// baseline (speedup 1.0000x reference)
#include <cuda_runtime.h>
#include <cuda_bf16.h>
#include <cstdint>
#include <math.h>

// ---------------- problem constants ----------------
#define TT 4096
#define DDIM 2048
#define IDIM 1024
#define EE 8
#define RTOT (2*TT)
#define GTOT (RTOT+TT)

// ---------------- GEMM tiling ----------------
// CTA: 256 thr = 8 warps (2 wm x 4 wn), warp tile 64m x 64n, CTA tile 128m x 256n
#define KT 32
#define ROW_B 80                 // 64B data + 16B pad; stride 20 words -> conflict-free ldmatrix
#define ARRA (128 * ROW_B)       // 10240  (A hi or lo)
#define ARRB (256 * ROW_B)       // 20480  (B hi or lo)
#define STAGE_B (2*ARRA + 2*ARRB)  // 61440
#define NSTG 3
#define SMEM_BYTES (NSTG * STAGE_B) // 184320
#define NCHUNK 12                // 16B cp.async chunks per thread per k-tile

// ---------------- scratch ----------------
__device__ unsigned short g_xhi[(size_t)TT * DDIM];
__device__ unsigned short g_xlo[(size_t)TT * DDIM];
__device__ unsigned short g_bguh[(size_t)9 * 2048 * 2048];  // gate_up^T [e][n][k] hi
__device__ unsigned short g_bgul[(size_t)9 * 2048 * 2048];
__device__ unsigned short g_bdnh[(size_t)9 * 2048 * 1024];  // down^T [e][n][k] hi
__device__ unsigned short g_bdnl[(size_t)9 * 2048 * 1024];
__device__ unsigned short g_rhh[(size_t)GTOT * 1024];       // h split hi
__device__ unsigned short g_rhl[(size_t)GTOT * 1024];
__device__ float g_do[(size_t)GTOT * 2048];                 // down out per slot
__device__ int   g_e0[TT], g_e1[TT];
__device__ float g_p0[TT], g_p1[TT];
__device__ int   g_cnt[EE];
__device__ int   g_off[EE];
__device__ int   g_ltok[EE * TT];
__device__ float g_lp[EE * TT];
__device__ int   g_sl0[TT], g_sl1[TT];

__device__ __forceinline__ float siluf(float v) { return v / (1.0f + __expf(-v)); }

__device__ __forceinline__ void splitbf(float v, unsigned short& h, unsigned short& l) {
    __nv_bfloat16 bh = __float2bfloat16(v);
    float rem = v - __bfloat162float(bh);
    __nv_bfloat16 bl = __float2bfloat16(rem);
    h = __bfloat16_as_ushort(bh);
    l = __bfloat16_as_ushort(bl);
}

__device__ __forceinline__ uint32_t smem_u32(const void* p) {
    uint32_t a;
    asm("{ .reg .u64 t; cvta.to.shared.u64 t, %1; cvt.u32.u64 %0, t; }" : "=r"(a) : "l"(p));
    return a;
}

#define CP16(dst, src) \
    asm volatile("cp.async.cg.shared.global [%0], [%1], 16;" :: "r"(dst), "l"(src) : "memory")
#define CP_COMMIT() asm volatile("cp.async.commit_group;" ::: "memory")
#define CP_WAIT(n)  asm volatile("cp.async.wait_group %0;" :: "n"(n) : "memory")

__device__ __forceinline__ void mma16(float* c, const uint32_t* a, const uint32_t* b) {
    asm volatile(
        "mma.sync.aligned.m16n8k16.row.col.f32.bf16.bf16.f32 "
        "{%0,%1,%2,%3}, {%4,%5,%6,%7}, {%8,%9}, {%0,%1,%2,%3};"
        : "+f"(c[0]), "+f"(c[1]), "+f"(c[2]), "+f"(c[3])
        : "r"(a[0]), "r"(a[1]), "r"(a[2]), "r"(a[3]), "r"(b[0]), "r"(b[1]));
}

__device__ __forceinline__ void ldsm4(uint32_t* r, uint32_t addr) {
    asm volatile("ldmatrix.sync.aligned.m8n8.x4.shared.b16 {%0,%1,%2,%3}, [%4];"
        : "=r"(r[0]), "=r"(r[1]), "=r"(r[2]), "=r"(r[3]) : "r"(addr));
}
__device__ __forceinline__ void ldsm2(uint32_t* r, uint32_t addr) {
    asm volatile("ldmatrix.sync.aligned.m8n8.x2.shared.b16 {%0,%1}, [%2];"
        : "=r"(r[0]), "=r"(r[1]) : "r"(addr));
}

// ---------------- launch 0: router ----------------
__global__ void router_kernel(const float* __restrict__ x, const float* __restrict__ rw) {
    int gwarp = (blockIdx.x * blockDim.x + threadIdx.x) >> 5;
    int lane = threadIdx.x & 31;
    if (gwarp >= TT) return;
    const float* xr = x + (size_t)gwarp * DDIM;
    float acc[8] = {0.f,0.f,0.f,0.f,0.f,0.f,0.f,0.f};
    for (int d = lane; d < DDIM; d += 32) {
        float xv = xr[d];
        const float4* r4 = (const float4*)(rw + (size_t)d * EE);
        float4 a = r4[0], b = r4[1];
        acc[0] += xv * a.x; acc[1] += xv * a.y; acc[2] += xv * a.z; acc[3] += xv * a.w;
        acc[4] += xv * b.x; acc[5] += xv * b.y; acc[6] += xv * b.z; acc[7] += xv * b.w;
    }
    #pragma unroll
    for (int e = 0; e < 8; e++)
        #pragma unroll
        for (int s = 16; s > 0; s >>= 1)
            acc[e] += __shfl_xor_sync(0xffffffffu, acc[e], s);
    if (lane == 0) {
        int i0 = 0; float v0 = acc[0];
        #pragma unroll
        for (int e = 1; e < 8; e++) if (acc[e] > v0) { v0 = acc[e]; i0 = e; }
        int i1 = -1; float v1 = -3.4e38f;
        #pragma unroll
        for (int e = 0; e < 8; e++) if (e != i0 && acc[e] > v1) { v1 = acc[e]; i1 = e; }
        g_e0[gwarp] = i0; g_e1[gwarp] = i1;
        g_p0[gwarp] = 1.0f / (1.0f + __expf(-v0));
        g_p1[gwarp] = 1.0f / (1.0f + __expf(-v1));
    }
}

// ---------------- launch 1: deterministic compaction ----------------
__global__ void build_lists_kernel() {
    int e = blockIdx.x;
    int tid = threadIdx.x;
    int lane = tid & 31, wid = tid >> 5;
    __shared__ int wsum[8];
    __shared__ int base_s;
    if (tid == 0) base_s = 0;
    __syncthreads();
    for (int t0 = 0; t0 < TT; t0 += 256) {
        int t = t0 + tid;
        bool sel = false; float p = 0.f; bool first = false;
        if (g_e0[t] == e)      { sel = true; p = g_p0[t]; first = true; }
        else if (g_e1[t] == e) { sel = true; p = g_p1[t]; }
        unsigned m = __ballot_sync(0xffffffffu, sel);
        int rank = __popc(m & ((1u << lane) - 1));
        if (lane == 0) wsum[wid] = __popc(m);
        __syncthreads();
        int woff = 0;
        #pragma unroll
        for (int w = 0; w < 8; w++) if (w < wid) woff += wsum[w];
        if (sel) {
            int idx = base_s + woff + rank;
            g_ltok[e * TT + idx] = t;
            g_lp[e * TT + idx]   = p;
            if (first) g_sl0[t] = idx; else g_sl1[t] = idx;
        }
        __syncthreads();
        if (tid == 0) {
            int tot = 0;
            #pragma unroll
            for (int w = 0; w < 8; w++) tot += wsum[w];
            base_s += tot;
        }
        __syncthreads();
    }
    if (tid == 0) g_cnt[e] = base_s;
}

// ---------------- launch 2: all conversions + offsets ----------------
#define NB_SPLIT 8192
#define NB_GU    36864
#define NB_DN    18432
__global__ void conv_all(const float* __restrict__ x,
                         const float* __restrict__ guw,
                         const float* __restrict__ dw,
                         const float* __restrict__ sgw,
                         const float* __restrict__ suw,
                         const float* __restrict__ sdw) {
    __shared__ float tile[32][33];
    const int b = blockIdx.x;
    const int tid = threadIdx.x;

    if (b == 0 && tid == 0) {
        int o = 0;
        #pragma unroll
        for (int e = 0; e < EE; e++) { g_off[e] = o; o += g_cnt[e]; }
    }

    if (b < NB_SPLIT) {
        size_t i = ((size_t)b * 256 + tid) * 4;
        float4 v = *(const float4*)(x + i);
        ushort4 h, l;
        splitbf(v.x, h.x, l.x); splitbf(v.y, h.y, l.y);
        splitbf(v.z, h.z, l.z); splitbf(v.w, h.w, l.w);
        *(ushort4*)(g_xhi + i) = h;
        *(ushort4*)(g_xlo + i) = l;
        return;
    }
    const int tx = tid & 31, ty = tid >> 5;
    if (b < NB_SPLIT + NB_GU) {
        int bb = b - NB_SPLIT;
        int bx = bb & 63, by = (bb >> 6) & 63, e = bb >> 12;
        int n0 = bx * 32, k0 = by * 32;
        const float* src; int ld, nsrc0;
        if (e < 8)          { src = guw + (size_t)e * 2048 * 2048; ld = 2048; nsrc0 = n0; }
        else if (n0 < 1024) { src = sgw; ld = 1024; nsrc0 = n0; }
        else                { src = suw; ld = 1024; nsrc0 = n0 - 1024; }
        #pragma unroll
        for (int j = 0; j < 4; j++) {
            int k = k0 + ty + j * 8;
            tile[ty + j * 8][tx] = src[(size_t)k * ld + nsrc0 + tx];
        }
        __syncthreads();
        #pragma unroll
        for (int j = 0; j < 4; j++) {
            int n = n0 + ty + j * 8;
            float v = tile[tx][ty + j * 8];
            unsigned short h, l;
            splitbf(v, h, l);
            size_t di = ((size_t)e * 2048 + n) * 2048 + k0 + tx;
            g_bguh[di] = h; g_bgul[di] = l;
        }
        return;
    }
    {
        int bb = b - NB_SPLIT - NB_GU;
        int bx = bb & 63, by = (bb >> 6) & 31, e = bb >> 11;
        int n0 = bx * 32, k0 = by * 32;
        const float* src = (e < 8) ? (dw + (size_t)e * 1024 * 2048) : sdw;
        #pragma unroll
        for (int j = 0; j < 4; j++) {
            int k = k0 + ty + j * 8;
            tile[ty + j * 8][tx] = src[(size_t)k * 2048 + n0 + tx];
        }
        __syncthreads();
        #pragma unroll
        for (int j = 0; j < 4; j++) {
            int n = n0 + ty + j * 8;
            float v = tile[tx][ty + j * 8];
            unsigned short h, l;
            splitbf(v, h, l);
            size_t di = ((size_t)e * 2048 + n) * 1024 + k0 + tx;
            g_bdnh[di] = h; g_bdnl[di] = l;
        }
    }
}

// ---------------- mainloop body: warp tile 64x64, 96 MMA/k-tile ----------------
#define MAINLOOP_KTILE(base)                                                     \
    {                                                                            \
        const uint32_t Ah = (base) + aoff;                                       \
        const uint32_t Al = Ah + ARRA;                                           \
        const uint32_t Bh = (base) + 2 * ARRA + boff;                            \
        const uint32_t Bl = Bh + ARRB;                                           \
        _Pragma("unroll")                                                        \
        for (int s = 0; s < 2; s++) {                                            \
            uint32_t bhf[8][2], blf[8][2];                                       \
            _Pragma("unroll")                                                    \
            for (int ni = 0; ni < 8; ni++) {                                     \
                ldsm2(bhf[ni], Bh + ni * (8 * ROW_B) + s * 32);                  \
                ldsm2(blf[ni], Bl + ni * (8 * ROW_B) + s * 32);                  \
            }                                                                    \
            _Pragma("unroll")                                                    \
            for (int mi = 0; mi < 4; mi++) {                                     \
                uint32_t ah[4], al[4];                                           \
                ldsm4(ah, Ah + mi * (16 * ROW_B) + s * 32);                      \
                ldsm4(al, Al + mi * (16 * ROW_B) + s * 32);                      \
                _Pragma("unroll")                                                \
                for (int ni = 0; ni < 8; ni++) {                                 \
                    mma16(acc[mi][ni], ah, bhf[ni]);                             \
                    mma16(acc[mi][ni], ah, blf[ni]);                             \
                    mma16(acc[mi][ni], al, bhf[ni]);                             \
                }                                                                \
            }                                                                    \
        }                                                                        \
    }

#define PIPE_LOOP(NK, COMPUTE)                                                   \
    uint32_t so_c = 0, so_l = 2 * STAGE_B;                                       \
    for (int it = 0; it < (NK); it++) {                                          \
        CP_WAIT(1);                                                              \
        __syncthreads();                                                         \
        if (it + 2 < (NK)) {                                                     \
            _Pragma("unroll")                                                    \
            for (int i = 0; i < NCHUNK; i++) { CP16(dst[i] + so_l, src[i]); src[i] += 64; } \
        }                                                                        \
        CP_COMMIT();                                                             \
        so_l += STAGE_B; if (so_l == NSTG * STAGE_B) so_l = 0;                   \
        const uint32_t base = sb + so_c;                                         \
        so_c += STAGE_B; if (so_c == NSTG * STAGE_B) so_c = 0;                   \
        COMPUTE(base)                                                            \
    }

// ---------------- launch 3: fused gate_up GEMM + SiLU + bf16-split h ----------------
// CTA tile 128m x 256n (128 gate cols + 128 up cols interleaved per 16). grid (8, 32, 9)
__global__ void __launch_bounds__(256, 1)
gemm_gu_fused()
{
    const int KD = 2048;
    extern __shared__ char smem[];
    const uint32_t sb = smem_u32(smem);
    const int tid = threadIdx.x;
    const int e = blockIdx.z;
    const int row0 = blockIdx.y * 128;
    const int col0g = blockIdx.x * 128;   // gate col base (up = 1024 + same)

    int M, soff;
    const float* lpp = nullptr;
    const int* ltok = nullptr;
    if (e < 8) { M = g_cnt[e]; soff = g_off[e]; ltok = g_ltok + e * TT; lpp = g_lp + e * TT; }
    else       { M = TT; soff = RTOT; }
    if (row0 >= M) return;

    // cp.async plan: 12 chunks/thread (A: 1024 chunks, B: 2048 chunks)
    const char* src[NCHUNK]; uint32_t dst[NCHUNK];
    #pragma unroll
    for (int i = 0; i < NCHUNK; i++) {
        int idx = tid + i * 256;
        const unsigned short* rowp;
        if (idx < 1024) {        // A side
            int arr = idx >> 9, ci = idx & 511;
            int r = ci >> 2, ch = ci & 3;
            int gr = row0 + r;
            size_t tok = (e < 8) ? (size_t)((gr < M) ? ltok[gr] : 0) : (size_t)gr;
            rowp = ((arr == 0) ? g_xhi : g_xlo) + tok * DDIM;
            src[i] = (const char*)rowp + ch * 16;
            dst[i] = sb + (uint32_t)(arr * ARRA + r * ROW_B + ch * 16);
        } else {                 // B side: 256 rows = 8 groups of (16 gate + 16 up)
            int bi = idx - 1024;
            int arr = bi >> 10, ci = bi & 1023;
            int r = ci >> 2, ch = ci & 3;
            int grp = r >> 5, w = r & 31;
            int ncol = (w < 16) ? (col0g + grp * 16 + w)
                                : (1024 + col0g + grp * 16 + (w - 16));
            rowp = ((arr == 0) ? g_bguh : g_bgul) + ((size_t)e * 2048 + ncol) * (size_t)KD;
            src[i] = (const char*)rowp + ch * 16;
            dst[i] = sb + (uint32_t)(2 * ARRA + arr * ARRB + r * ROW_B + ch * 16);
        }
    }

    const int lane = tid & 31;
    const int g = lane >> 2, t = lane & 3;
    const int wm = (tid >> 5) & 1, wn = (tid >> 5) >> 1;   // 2 x 4 warps

    const uint32_t aoff = (uint32_t)((wm * 64 + (lane & 7) + ((lane >> 3) & 1) * 8) * ROW_B
                                     + (lane >> 4) * 16);
    const uint32_t boff = (uint32_t)((wn * 64 + (lane & 7)) * ROW_B + ((lane >> 3) & 1) * 16);

    float acc[4][8][4];
    #pragma unroll
    for (int mi = 0; mi < 4; mi++)
        #pragma unroll
        for (int ni = 0; ni < 8; ni++)
            #pragma unroll
            for (int r = 0; r < 4; r++) acc[mi][ni][r] = 0.f;

    // prologue: tiles 0,1 into stages 0,1
    #pragma unroll
    for (int i = 0; i < NCHUNK; i++) { CP16(dst[i], src[i]); src[i] += 64; }
    CP_COMMIT();
    #pragma unroll
    for (int i = 0; i < NCHUNK; i++) { CP16(dst[i] + STAGE_B, src[i]); src[i] += 64; }
    CP_COMMIT();

    const int NK = KD / KT;   // 64
    PIPE_LOOP(NK, MAINLOOP_KTILE)

    // fused epilogue: h = silu(p*gate) * (p*up), split bf16, store
    // gate acc at ni in {0,1,4,5}, pairs with up at ni+2
    #pragma unroll
    for (int mi = 0; mi < 4; mi++) {
        int grb = row0 + wm * 64 + mi * 16 + g;
        #pragma unroll
        for (int pass = 0; pass < 2; pass++) {
            int gr = grb + pass * 8;
            if (gr < M) {
                float p = (e < 8) ? lpp[gr] : 1.f;
                size_t slot = (size_t)(soff + gr);
                #pragma unroll
                for (int pb = 0; pb < 2; pb++) {      // pb: 0 -> ni {0,1}, 1 -> ni {4,5}
                    #pragma unroll
                    for (int j = 0; j < 2; j++) {
                        int ni = pb * 4 + j;
                        float gv0 = p * acc[mi][ni][pass * 2 + 0];
                        float gv1 = p * acc[mi][ni][pass * 2 + 1];
                        float uv0 = p * acc[mi][ni + 2][pass * 2 + 0];
                        float uv1 = p * acc[mi][ni + 2][pass * 2 + 1];
                        float h0 = siluf(gv0) * uv0;
                        float h1 = siluf(gv1) * uv1;
                        unsigned short h0h, h0l, h1h, h1l;
                        splitbf(h0, h0h, h0l);
                        splitbf(h1, h1h, h1l);
                        int col = col0g + (2 * wn + pb) * 16 + j * 8 + 2 * t;
                        ushort2 hh; hh.x = h0h; hh.y = h1h;
                        ushort2 hl; hl.x = h0l; hl.y = h1l;
                        *(ushort2*)(g_rhh + slot * 1024 + col) = hh;
                        *(ushort2*)(g_rhl + slot * 1024 + col) = hl;
                    }
                }
            }
        }
    }
}

// ---------------- launch 4: down GEMM, plain slot stores. grid (8, 32, 9) ----------------
__global__ void __launch_bounds__(256, 1)
gemm_down()
{
    const int KD = 1024;
    extern __shared__ char smem[];
    const uint32_t sb = smem_u32(smem);
    const int tid = threadIdx.x;
    const int e = blockIdx.z;
    const int row0 = blockIdx.y * 128;
    const int col0 = blockIdx.x * 256;

    int M, soff;
    if (e < 8) { M = g_cnt[e]; soff = g_off[e]; } else { M = TT; soff = RTOT; }
    if (row0 >= M) return;

    const char* src[NCHUNK]; uint32_t dst[NCHUNK];
    #pragma unroll
    for (int i = 0; i < NCHUNK; i++) {
        int idx = tid + i * 256;
        const unsigned short* rowp;
        if (idx < 1024) {
            int arr = idx >> 9, ci = idx & 511;
            int r = ci >> 2, ch = ci & 3;
            int gr = row0 + r;
            size_t slot = (size_t)(soff + ((gr < M) ? gr : 0));
            rowp = ((arr == 0) ? g_rhh : g_rhl) + slot * 1024;
            src[i] = (const char*)rowp + ch * 16;
            dst[i] = sb + (uint32_t)(arr * ARRA + r * ROW_B + ch * 16);
        } else {
            int bi = idx - 1024;
            int arr = bi >> 10, ci = bi & 1023;
            int r = ci >> 2, ch = ci & 3;
            rowp = ((arr == 0) ? g_bdnh : g_bdnl) + ((size_t)e * 2048 + col0 + r) * (size_t)KD;
            src[i] = (const char*)rowp + ch * 16;
            dst[i] = sb + (uint32_t)(2 * ARRA + arr * ARRB + r * ROW_B + ch * 16);
        }
    }

    const int lane = tid & 31;
    const int g = lane >> 2, t = lane & 3;
    const int wm = (tid >> 5) & 1, wn = (tid >> 5) >> 1;

    const uint32_t aoff = (uint32_t)((wm * 64 + (lane & 7) + ((lane >> 3) & 1) * 8) * ROW_B
                                     + (lane >> 4) * 16);
    const uint32_t boff = (uint32_t)((wn * 64 + (lane & 7)) * ROW_B + ((lane >> 3) & 1) * 16);

    float acc[4][8][4];
    #pragma unroll
    for (int mi = 0; mi < 4; mi++)
        #pragma unroll
        for (int ni = 0; ni < 8; ni++)
            #pragma unroll
            for (int r = 0; r < 4; r++) acc[mi][ni][r] = 0.f;

    #pragma unroll
    for (int i = 0; i < NCHUNK; i++) { CP16(dst[i], src[i]); src[i] += 64; }
    CP_COMMIT();
    #pragma unroll
    for (int i = 0; i < NCHUNK; i++) { CP16(dst[i] + STAGE_B, src[i]); src[i] += 64; }
    CP_COMMIT();

    const int NK = KD / KT;   // 32
    PIPE_LOOP(NK, MAINLOOP_KTILE)

    #pragma unroll
    for (int mi = 0; mi < 4; mi++) {
        int gr0 = row0 + wm * 64 + mi * 16 + g;
        int gr1 = gr0 + 8;
        bool v0 = gr0 < M, v1 = gr1 < M;
        float* d0 = g_do + (size_t)(soff + gr0) * 2048 + col0 + wn * 64;
        float* d1 = g_do + (size_t)(soff + gr1) * 2048 + col0 + wn * 64;
        #pragma unroll
        for (int ni = 0; ni < 8; ni++) {
            int cc = ni * 8 + 2 * t;
            if (v0) { float2 v; v.x = acc[mi][ni][0]; v.y = acc[mi][ni][1]; *(float2*)(d0 + cc) = v; }
            if (v1) { float2 v; v.x = acc[mi][ni][2]; v.y = acc[mi][ni][3]; *(float2*)(d1 + cc) = v; }
        }
    }
}

// ---------------- launch 5: combine ----------------
__global__ void combine_kernel(float* __restrict__ out) {
    int t = blockIdx.x;
    int c = threadIdx.x * 8;
    int s0 = g_off[g_e0[t]] + g_sl0[t];
    int s1 = g_off[g_e1[t]] + g_sl1[t];
    const float* pa = g_do + (size_t)(RTOT + t) * 2048 + c;
    const float* pb = g_do + (size_t)s0 * 2048 + c;
    const float* pc = g_do + (size_t)s1 * 2048 + c;
    float* po = out + (size_t)t * 2048 + c;
    #pragma unroll
    for (int j = 0; j < 2; j++) {
        float4 a = *(const float4*)(pa + j * 4);
        float4 b = *(const float4*)(pb + j * 4);
        float4 d = *(const float4*)(pc + j * 4);
        float4 o;
        o.x = a.x + b.x + d.x; o.y = a.y + b.y + d.y;
        o.z = a.z + b.z + d.z; o.w = a.w + b.w + d.w;
        *(float4*)(po + j * 4) = o;
    }
}

// ---------------- launch ----------------
extern "C" void kernel_launch(void* const* d_in, const int* in_sizes, int n_in,
                              void* d_out, int out_size) {
    const float* x   = (const float*)d_in[0];
    const float* rw  = (const float*)d_in[1];
    const float* guw = (const float*)d_in[2];
    const float* dw  = (const float*)d_in[3];
    const float* sgw = (const float*)d_in[4];
    const float* suw = (const float*)d_in[5];
    const float* sdw = (const float*)d_in[6];
    float* out = (float*)d_out;

    cudaFuncSetAttribute(gemm_gu_fused, cudaFuncAttributeMaxDynamicSharedMemorySize, SMEM_BYTES);
    cudaFuncSetAttribute(gemm_down,     cudaFuncAttributeMaxDynamicSharedMemorySize, SMEM_BYTES);

    router_kernel<<<TT / 8, 256>>>(x, rw);                                    // #0
    build_lists_kernel<<<EE, 256>>>();                                        // #1
    conv_all<<<NB_SPLIT + NB_GU + NB_DN, 256>>>(x, guw, dw, sgw, suw, sdw);   // #2
    gemm_gu_fused<<<dim3(8, 32, 9), 256, SMEM_BYTES>>>();                     // #3 (profiled)
    gemm_down<<<dim3(8, 32, 9), 256, SMEM_BYTES>>>();                         // #4
    combine_kernel<<<TT, 256>>>(out);                                         // #5
}

// round 12
// speedup vs baseline: 1.1277x; 1.1277x over previous
#include <cuda_runtime.h>
#include <cuda_bf16.h>
#include <cstdint>
#include <math.h>

// ---------------- problem constants ----------------
#define TT 4096
#define DDIM 2048
#define IDIM 1024
#define EE 8
#define RTOT (2*TT)
#define GTOT (RTOT+TT)

// ---------------- GEMM tiling (R8 config: CTA 128x128, 8 warps 2x4, warp 64x32) ----------------
#define KT 32
#define ROW_B 80                 // padded row: 32 bf16 (64B) + 16B pad; stride 20 words -> conflict-free
#define ARR_B (128 * ROW_B)
#define STAGE_B (4 * ARR_B)      // Ahi|Alo|Bhi|Blo = 40960
#define SMEM_BYTES (2 * STAGE_B) // 81920

// ---------------- scratch ----------------
__device__ unsigned short g_xhi[(size_t)TT * DDIM];
__device__ unsigned short g_xlo[(size_t)TT * DDIM];
__device__ unsigned short g_bguh[(size_t)9 * 2048 * 2048];  // gate_up^T [e][n][k] hi
__device__ unsigned short g_bgul[(size_t)9 * 2048 * 2048];
__device__ unsigned short g_bdnh[(size_t)9 * 2048 * 1024];  // down^T [e][n][k] hi
__device__ unsigned short g_bdnl[(size_t)9 * 2048 * 1024];
__device__ unsigned short g_rhh[(size_t)GTOT * 1024];       // h split hi
__device__ unsigned short g_rhl[(size_t)GTOT * 1024];
__device__ float g_do[(size_t)GTOT * 2048];                 // down out per slot
__device__ int   g_e0[TT], g_e1[TT];
__device__ float g_p0[TT], g_p1[TT];
__device__ int   g_cnt[EE];
__device__ int   g_off[EE];
__device__ int   g_ltok[EE * TT];
__device__ float g_lp[EE * TT];
__device__ int   g_sl0[TT], g_sl1[TT];

__device__ __forceinline__ float siluf(float v) { return v / (1.0f + __expf(-v)); }

__device__ __forceinline__ void splitbf(float v, unsigned short& h, unsigned short& l) {
    __nv_bfloat16 bh = __float2bfloat16(v);
    float rem = v - __bfloat162float(bh);
    __nv_bfloat16 bl = __float2bfloat16(rem);
    h = __bfloat16_as_ushort(bh);
    l = __bfloat16_as_ushort(bl);
}

__device__ __forceinline__ uint32_t smem_u32(const void* p) {
    uint32_t a;
    asm("{ .reg .u64 t; cvta.to.shared.u64 t, %1; cvt.u32.u64 %0, t; }" : "=r"(a) : "l"(p));
    return a;
}

#define CP16(dst, src) \
    asm volatile("cp.async.cg.shared.global [%0], [%1], 16;" :: "r"(dst), "l"(src) : "memory")
#define CP_COMMIT() asm volatile("cp.async.commit_group;" ::: "memory")
#define CP_WAIT(n)  asm volatile("cp.async.wait_group %0;" :: "n"(n) : "memory")

__device__ __forceinline__ void mma16(float* c, const uint32_t* a, const uint32_t* b) {
    asm volatile(
        "mma.sync.aligned.m16n8k16.row.col.f32.bf16.bf16.f32 "
        "{%0,%1,%2,%3}, {%4,%5,%6,%7}, {%8,%9}, {%0,%1,%2,%3};"
        : "+f"(c[0]), "+f"(c[1]), "+f"(c[2]), "+f"(c[3])
        : "r"(a[0]), "r"(a[1]), "r"(a[2]), "r"(a[3]), "r"(b[0]), "r"(b[1]));
}

__device__ __forceinline__ void ldsm4(uint32_t* r, uint32_t addr) {
    asm volatile("ldmatrix.sync.aligned.m8n8.x4.shared.b16 {%0,%1,%2,%3}, [%4];"
        : "=r"(r[0]), "=r"(r[1]), "=r"(r[2]), "=r"(r[3]) : "r"(addr));
}
__device__ __forceinline__ void ldsm2(uint32_t* r, uint32_t addr) {
    asm volatile("ldmatrix.sync.aligned.m8n8.x2.shared.b16 {%0,%1}, [%2];"
        : "=r"(r[0]), "=r"(r[1]) : "r"(addr));
}

// ---------------- launch 0: router ----------------
__global__ void router_kernel(const float* __restrict__ x, const float* __restrict__ rw) {
    int gwarp = (blockIdx.x * blockDim.x + threadIdx.x) >> 5;
    int lane = threadIdx.x & 31;
    if (gwarp >= TT) return;
    const float* xr = x + (size_t)gwarp * DDIM;
    float acc[8] = {0.f,0.f,0.f,0.f,0.f,0.f,0.f,0.f};
    for (int d = lane; d < DDIM; d += 32) {
        float xv = xr[d];
        const float4* r4 = (const float4*)(rw + (size_t)d * EE);
        float4 a = r4[0], b = r4[1];
        acc[0] += xv * a.x; acc[1] += xv * a.y; acc[2] += xv * a.z; acc[3] += xv * a.w;
        acc[4] += xv * b.x; acc[5] += xv * b.y; acc[6] += xv * b.z; acc[7] += xv * b.w;
    }
    #pragma unroll
    for (int e = 0; e < 8; e++)
        #pragma unroll
        for (int s = 16; s > 0; s >>= 1)
            acc[e] += __shfl_xor_sync(0xffffffffu, acc[e], s);
    if (lane == 0) {
        int i0 = 0; float v0 = acc[0];
        #pragma unroll
        for (int e = 1; e < 8; e++) if (acc[e] > v0) { v0 = acc[e]; i0 = e; }
        int i1 = -1; float v1 = -3.4e38f;
        #pragma unroll
        for (int e = 0; e < 8; e++) if (e != i0 && acc[e] > v1) { v1 = acc[e]; i1 = e; }
        g_e0[gwarp] = i0; g_e1[gwarp] = i1;
        g_p0[gwarp] = 1.0f / (1.0f + __expf(-v0));
        g_p1[gwarp] = 1.0f / (1.0f + __expf(-v1));
    }
}

// ---------------- launch 1: deterministic compaction ----------------
__global__ void build_lists_kernel() {
    int e = blockIdx.x;
    int tid = threadIdx.x;
    int lane = tid & 31, wid = tid >> 5;
    __shared__ int wsum[8];
    __shared__ int base_s;
    if (tid == 0) base_s = 0;
    __syncthreads();
    for (int t0 = 0; t0 < TT; t0 += 256) {
        int t = t0 + tid;
        bool sel = false; float p = 0.f; bool first = false;
        if (g_e0[t] == e)      { sel = true; p = g_p0[t]; first = true; }
        else if (g_e1[t] == e) { sel = true; p = g_p1[t]; }
        unsigned m = __ballot_sync(0xffffffffu, sel);
        int rank = __popc(m & ((1u << lane) - 1));
        if (lane == 0) wsum[wid] = __popc(m);
        __syncthreads();
        int woff = 0;
        #pragma unroll
        for (int w = 0; w < 8; w++) if (w < wid) woff += wsum[w];
        if (sel) {
            int idx = base_s + woff + rank;
            g_ltok[e * TT + idx] = t;
            g_lp[e * TT + idx]   = p;
            if (first) g_sl0[t] = idx; else g_sl1[t] = idx;
        }
        __syncthreads();
        if (tid == 0) {
            int tot = 0;
            #pragma unroll
            for (int w = 0; w < 8; w++) tot += wsum[w];
            base_s += tot;
        }
        __syncthreads();
    }
    if (tid == 0) g_cnt[e] = base_s;
}

// ---------------- launch 2: all conversions + offsets ----------------
#define NB_SPLIT 8192
#define NB_GU    36864
#define NB_DN    18432
__global__ void conv_all(const float* __restrict__ x,
                         const float* __restrict__ guw,
                         const float* __restrict__ dw,
                         const float* __restrict__ sgw,
                         const float* __restrict__ suw,
                         const float* __restrict__ sdw) {
    __shared__ float tile[32][33];
    const int b = blockIdx.x;
    const int tid = threadIdx.x;

    if (b == 0 && tid == 0) {
        int o = 0;
        #pragma unroll
        for (int e = 0; e < EE; e++) { g_off[e] = o; o += g_cnt[e]; }
    }

    if (b < NB_SPLIT) {
        size_t i = ((size_t)b * 256 + tid) * 4;
        float4 v = *(const float4*)(x + i);
        ushort4 h, l;
        splitbf(v.x, h.x, l.x); splitbf(v.y, h.y, l.y);
        splitbf(v.z, h.z, l.z); splitbf(v.w, h.w, l.w);
        *(ushort4*)(g_xhi + i) = h;
        *(ushort4*)(g_xlo + i) = l;
        return;
    }
    const int tx = tid & 31, ty = tid >> 5;
    if (b < NB_SPLIT + NB_GU) {
        int bb = b - NB_SPLIT;
        int bx = bb & 63, by = (bb >> 6) & 63, e = bb >> 12;
        int n0 = bx * 32, k0 = by * 32;
        const float* src; int ld, nsrc0;
        if (e < 8)          { src = guw + (size_t)e * 2048 * 2048; ld = 2048; nsrc0 = n0; }
        else if (n0 < 1024) { src = sgw; ld = 1024; nsrc0 = n0; }
        else                { src = suw; ld = 1024; nsrc0 = n0 - 1024; }
        #pragma unroll
        for (int j = 0; j < 4; j++) {
            int k = k0 + ty + j * 8;
            tile[ty + j * 8][tx] = src[(size_t)k * ld + nsrc0 + tx];
        }
        __syncthreads();
        #pragma unroll
        for (int j = 0; j < 4; j++) {
            int n = n0 + ty + j * 8;
            float v = tile[tx][ty + j * 8];
            unsigned short h, l;
            splitbf(v, h, l);
            size_t di = ((size_t)e * 2048 + n) * 2048 + k0 + tx;
            g_bguh[di] = h; g_bgul[di] = l;
        }
        return;
    }
    {
        int bb = b - NB_SPLIT - NB_GU;
        int bx = bb & 63, by = (bb >> 6) & 31, e = bb >> 11;
        int n0 = bx * 32, k0 = by * 32;
        const float* src = (e < 8) ? (dw + (size_t)e * 1024 * 2048) : sdw;
        #pragma unroll
        for (int j = 0; j < 4; j++) {
            int k = k0 + ty + j * 8;
            tile[ty + j * 8][tx] = src[(size_t)k * 2048 + n0 + tx];
        }
        __syncthreads();
        #pragma unroll
        for (int j = 0; j < 4; j++) {
            int n = n0 + ty + j * 8;
            float v = tile[tx][ty + j * 8];
            unsigned short h, l;
            splitbf(v, h, l);
            size_t di = ((size_t)e * 2048 + n) * 1024 + k0 + tx;
            g_bdnh[di] = h; g_bdnl[di] = l;
        }
    }
}

// ---------------- mainloop: warp tile 64x32, RAW-chain-free MMA ordering ----------------
// Per (s, mi): 3 ni-sweeps (ah*bh, ah*bl, al*bh) -> same-acc reuse distance = 4 MMAs
#define MAINLOOP_KTILE(base)                                                     \
    {                                                                            \
        const uint32_t Ah = (base) + aoff;                                       \
        const uint32_t Al = Ah + ARR_B;                                          \
        const uint32_t Bh = (base) + 2 * ARR_B + boff;                           \
        const uint32_t Bl = Bh + ARR_B;                                          \
        _Pragma("unroll")                                                        \
        for (int s = 0; s < 2; s++) {                                            \
            uint32_t bhf[4][2], blf[4][2];                                       \
            _Pragma("unroll")                                                    \
            for (int ni = 0; ni < 4; ni++) {                                     \
                ldsm2(bhf[ni], Bh + ni * (8 * ROW_B) + s * 32);                  \
                ldsm2(blf[ni], Bl + ni * (8 * ROW_B) + s * 32);                  \
            }                                                                    \
            _Pragma("unroll")                                                    \
            for (int mi = 0; mi < 4; mi++) {                                     \
                uint32_t ah[4], al[4];                                           \
                ldsm4(ah, Ah + mi * (16 * ROW_B) + s * 32);                      \
                ldsm4(al, Al + mi * (16 * ROW_B) + s * 32);                      \
                _Pragma("unroll")                                                \
                for (int ni = 0; ni < 4; ni++) mma16(acc[mi][ni], ah, bhf[ni]);  \
                _Pragma("unroll")                                                \
                for (int ni = 0; ni < 4; ni++) mma16(acc[mi][ni], ah, blf[ni]);  \
                _Pragma("unroll")                                                \
                for (int ni = 0; ni < 4; ni++) mma16(acc[mi][ni], al, bhf[ni]);  \
            }                                                                    \
        }                                                                        \
    }

// ---------------- launch 3: fused gate_up GEMM + SiLU + bf16-split h ----------------
// Tile: 128 rows x (64 gate cols + 64 up cols paired). grid (16, 32, 9)
__global__ void __launch_bounds__(256, 2)
gemm_gu_fused()
{
    const int KD = 2048;
    extern __shared__ char smem[];
    const uint32_t sb = smem_u32(smem);
    const int tid = threadIdx.x;
    const int e = blockIdx.z;
    const int row0 = blockIdx.y * 128;
    const int col0g = blockIdx.x * 64;

    int M, soff;
    const float* lpp = nullptr;
    const int* ltok = nullptr;
    if (e < 8) { M = g_cnt[e]; soff = g_off[e]; ltok = g_ltok + e * TT; lpp = g_lp + e * TT; }
    else       { M = TT; soff = RTOT; }
    if (row0 >= M) return;

    const char* src[8]; uint32_t dst[8];
    #pragma unroll
    for (int i = 0; i < 8; i++) {
        int idx = tid + i * 256;
        int arr = idx >> 9;
        int ci = idx & 511;
        int r = ci >> 2, ch = ci & 3;
        const unsigned short* rowp;
        if (arr <= 1) {
            int gr = row0 + r;
            size_t tok = (e < 8) ? (size_t)((gr < M) ? ltok[gr] : 0) : (size_t)gr;
            rowp = ((arr == 0) ? g_xhi : g_xlo) + tok * DDIM;
        } else {
            int grp = r >> 5, w = r & 31;
            int ncol = (w < 16) ? (col0g + grp * 16 + w)
                                : (1024 + col0g + grp * 16 + (w - 16));
            rowp = ((arr == 2) ? g_bguh : g_bgul) + ((size_t)e * 2048 + ncol) * (size_t)KD;
        }
        src[i] = (const char*)rowp + ch * 16;
        dst[i] = sb + (uint32_t)(arr * ARR_B + r * ROW_B + ch * 16);
    }

    const int lane = tid & 31;
    const int g = lane >> 2, t = lane & 3;
    const int wm = (tid >> 5) & 1, wn = (tid >> 5) >> 1;

    const uint32_t aoff = (uint32_t)((wm * 64 + (lane & 7) + ((lane >> 3) & 1) * 8) * ROW_B
                                     + (lane >> 4) * 16);
    const uint32_t boff = (uint32_t)((wn * 32 + (lane & 7)) * ROW_B + ((lane >> 3) & 1) * 16);

    float acc[4][4][4];
    #pragma unroll
    for (int mi = 0; mi < 4; mi++)
        #pragma unroll
        for (int ni = 0; ni < 4; ni++)
            #pragma unroll
            for (int r = 0; r < 4; r++) acc[mi][ni][r] = 0.f;

    #pragma unroll
    for (int i = 0; i < 8; i++) { CP16(dst[i], src[i]); src[i] += 64; }
    CP_COMMIT();

    const int NK = KD / KT;
    for (int it = 0; it < NK; it++) {
        CP_WAIT(0);
        __syncthreads();
        if (it + 1 < NK) {
            uint32_t so = (uint32_t)(((it + 1) & 1) * STAGE_B);
            #pragma unroll
            for (int i = 0; i < 8; i++) { CP16(dst[i] + so, src[i]); src[i] += 64; }
            CP_COMMIT();
        }
        const uint32_t base = sb + (uint32_t)((it & 1) * STAGE_B);
        MAINLOOP_KTILE(base)
    }

    // fused epilogue: h = silu(p*gate) * (p*up), split to bf16, store
    #pragma unroll
    for (int mi = 0; mi < 4; mi++) {
        int grb = row0 + wm * 64 + mi * 16 + g;
        #pragma unroll
        for (int pass = 0; pass < 2; pass++) {
            int gr = grb + pass * 8;
            if (gr < M) {
                float p = (e < 8) ? lpp[gr] : 1.f;
                size_t slot = (size_t)(soff + gr);
                #pragma unroll
                for (int ni = 0; ni < 2; ni++) {
                    float gv0 = p * acc[mi][ni][pass * 2 + 0];
                    float gv1 = p * acc[mi][ni][pass * 2 + 1];
                    float uv0 = p * acc[mi][ni + 2][pass * 2 + 0];
                    float uv1 = p * acc[mi][ni + 2][pass * 2 + 1];
                    float h0 = siluf(gv0) * uv0;
                    float h1 = siluf(gv1) * uv1;
                    unsigned short h0h, h0l, h1h, h1l;
                    splitbf(h0, h0h, h0l);
                    splitbf(h1, h1h, h1l);
                    int col = col0g + wn * 16 + ni * 8 + 2 * t;
                    ushort2 hh; hh.x = h0h; hh.y = h1h;
                    ushort2 hl; hl.x = h0l; hl.y = h1l;
                    *(ushort2*)(g_rhh + slot * 1024 + col) = hh;
                    *(ushort2*)(g_rhl + slot * 1024 + col) = hl;
                }
            }
        }
    }
}

// ---------------- launch 4: down GEMM, plain slot stores. grid (16, 32, 9) ----------------
__global__ void __launch_bounds__(256, 2)
gemm_down()
{
    const int KD = 1024;
    extern __shared__ char smem[];
    const uint32_t sb = smem_u32(smem);
    const int tid = threadIdx.x;
    const int e = blockIdx.z;
    const int row0 = blockIdx.y * 128;
    const int col0 = blockIdx.x * 128;

    int M, soff;
    if (e < 8) { M = g_cnt[e]; soff = g_off[e]; } else { M = TT; soff = RTOT; }
    if (row0 >= M) return;

    const char* src[8]; uint32_t dst[8];
    #pragma unroll
    for (int i = 0; i < 8; i++) {
        int idx = tid + i * 256;
        int arr = idx >> 9;
        int ci = idx & 511;
        int r = ci >> 2, ch = ci & 3;
        const unsigned short* rowp;
        if (arr <= 1) {
            int gr = row0 + r;
            size_t slot = (size_t)(soff + ((gr < M) ? gr : 0));
            rowp = ((arr == 0) ? g_rhh : g_rhl) + slot * 1024;
        } else {
            rowp = ((arr == 2) ? g_bdnh : g_bdnl) + ((size_t)e * 2048 + col0 + r) * (size_t)KD;
        }
        src[i] = (const char*)rowp + ch * 16;
        dst[i] = sb + (uint32_t)(arr * ARR_B + r * ROW_B + ch * 16);
    }

    const int lane = tid & 31;
    const int g = lane >> 2, t = lane & 3;
    const int wm = (tid >> 5) & 1, wn = (tid >> 5) >> 1;

    const uint32_t aoff = (uint32_t)((wm * 64 + (lane & 7) + ((lane >> 3) & 1) * 8) * ROW_B
                                     + (lane >> 4) * 16);
    const uint32_t boff = (uint32_t)((wn * 32 + (lane & 7)) * ROW_B + ((lane >> 3) & 1) * 16);

    float acc[4][4][4];
    #pragma unroll
    for (int mi = 0; mi < 4; mi++)
        #pragma unroll
        for (int ni = 0; ni < 4; ni++)
            #pragma unroll
            for (int r = 0; r < 4; r++) acc[mi][ni][r] = 0.f;

    #pragma unroll
    for (int i = 0; i < 8; i++) { CP16(dst[i], src[i]); src[i] += 64; }
    CP_COMMIT();

    const int NK = KD / KT;
    for (int it = 0; it < NK; it++) {
        CP_WAIT(0);
        __syncthreads();
        if (it + 1 < NK) {
            uint32_t so = (uint32_t)(((it + 1) & 1) * STAGE_B);
            #pragma unroll
            for (int i = 0; i < 8; i++) { CP16(dst[i] + so, src[i]); src[i] += 64; }
            CP_COMMIT();
        }
        const uint32_t base = sb + (uint32_t)((it & 1) * STAGE_B);
        MAINLOOP_KTILE(base)
    }

    #pragma unroll
    for (int mi = 0; mi < 4; mi++) {
        int gr0 = row0 + wm * 64 + mi * 16 + g;
        int gr1 = gr0 + 8;
        bool v0 = gr0 < M, v1 = gr1 < M;
        float* d0 = g_do + (size_t)(soff + gr0) * 2048 + col0 + wn * 32;
        float* d1 = g_do + (size_t)(soff + gr1) * 2048 + col0 + wn * 32;
        #pragma unroll
        for (int ni = 0; ni < 4; ni++) {
            int cc = ni * 8 + 2 * t;
            if (v0) { float2 v; v.x = acc[mi][ni][0]; v.y = acc[mi][ni][1]; *(float2*)(d0 + cc) = v; }
            if (v1) { float2 v; v.x = acc[mi][ni][2]; v.y = acc[mi][ni][3]; *(float2*)(d1 + cc) = v; }
        }
    }
}

// ---------------- launch 5: combine ----------------
__global__ void combine_kernel(float* __restrict__ out) {
    int t = blockIdx.x;
    int c = threadIdx.x * 8;
    int s0 = g_off[g_e0[t]] + g_sl0[t];
    int s1 = g_off[g_e1[t]] + g_sl1[t];
    const float* pa = g_do + (size_t)(RTOT + t) * 2048 + c;
    const float* pb = g_do + (size_t)s0 * 2048 + c;
    const float* pc = g_do + (size_t)s1 * 2048 + c;
    float* po = out + (size_t)t * 2048 + c;
    #pragma unroll
    for (int j = 0; j < 2; j++) {
        float4 a = *(const float4*)(pa + j * 4);
        float4 b = *(const float4*)(pb + j * 4);
        float4 d = *(const float4*)(pc + j * 4);
        float4 o;
        o.x = a.x + b.x + d.x; o.y = a.y + b.y + d.y;
        o.z = a.z + b.z + d.z; o.w = a.w + b.w + d.w;
        *(float4*)(po + j * 4) = o;
    }
}

// ---------------- launch ----------------
extern "C" void kernel_launch(void* const* d_in, const int* in_sizes, int n_in,
                              void* d_out, int out_size) {
    const float* x   = (const float*)d_in[0];
    const float* rw  = (const float*)d_in[1];
    const float* guw = (const float*)d_in[2];
    const float* dw  = (const float*)d_in[3];
    const float* sgw = (const float*)d_in[4];
    const float* suw = (const float*)d_in[5];
    const float* sdw = (const float*)d_in[6];
    float* out = (float*)d_out;

    cudaFuncSetAttribute(gemm_gu_fused, cudaFuncAttributeMaxDynamicSharedMemorySize, SMEM_BYTES);
    cudaFuncSetAttribute(gemm_down,     cudaFuncAttributeMaxDynamicSharedMemorySize, SMEM_BYTES);

    router_kernel<<<TT / 8, 256>>>(x, rw);                                    // #0
    build_lists_kernel<<<EE, 256>>>();                                        // #1
    conv_all<<<NB_SPLIT + NB_GU + NB_DN, 256>>>(x, guw, dw, sgw, suw, sdw);   // #2
    gemm_gu_fused<<<dim3(16, 32, 9), 256, SMEM_BYTES>>>();                    // #3 (profiled)
    gemm_down<<<dim3(16, 32, 9), 256, SMEM_BYTES>>>();                        // #4
    combine_kernel<<<TT, 256>>>(out);                                         // #5
}

// round 13
// speedup vs baseline: 1.1414x; 1.0122x over previous
#include <cuda_runtime.h>
#include <cuda_bf16.h>
#include <cstdint>
#include <math.h>

// ---------------- problem constants ----------------
#define TT 4096
#define DDIM 2048
#define IDIM 1024
#define EE 8
#define RTOT (2*TT)
#define GTOT (RTOT+TT)

// ---------------- GEMM tiling: CTA 128 thr = 4 warps (2x2), warp 64x64, CTA tile 128x128 ----------------
#define KT 32
#define ROW_B 80                 // 64B data + 16B pad; stride 20 words -> conflict-free
#define ARR_B (128 * ROW_B)      // 10240 per operand array (A or B, hi or lo: 128 rows)
#define STAGE_B (4 * ARR_B)      // Ahi|Alo|Bhi|Blo = 40960
#define SMEM_BYTES (2 * STAGE_B) // 81920 (x2 CTAs = 163840 <= 228K)
#define NCHUNK 16                // 16B cp.async chunks per thread per k-tile (2048 chunks / 128 thr)

// ---------------- scratch ----------------
__device__ unsigned short g_xhi[(size_t)TT * DDIM];
__device__ unsigned short g_xlo[(size_t)TT * DDIM];
__device__ unsigned short g_bguh[(size_t)9 * 2048 * 2048];  // gate_up^T [e][n][k] hi
__device__ unsigned short g_bgul[(size_t)9 * 2048 * 2048];
__device__ unsigned short g_bdnh[(size_t)9 * 2048 * 1024];  // down^T [e][n][k] hi
__device__ unsigned short g_bdnl[(size_t)9 * 2048 * 1024];
__device__ unsigned short g_rhh[(size_t)GTOT * 1024];       // h split hi
__device__ unsigned short g_rhl[(size_t)GTOT * 1024];
__device__ float g_do[(size_t)GTOT * 2048];                 // down out per slot
__device__ int   g_e0[TT], g_e1[TT];
__device__ float g_p0[TT], g_p1[TT];
__device__ int   g_cnt[EE];
__device__ int   g_off[EE];
__device__ int   g_ltok[EE * TT];
__device__ float g_lp[EE * TT];
__device__ int   g_sl0[TT], g_sl1[TT];

__device__ __forceinline__ float siluf(float v) { return v / (1.0f + __expf(-v)); }

__device__ __forceinline__ void splitbf(float v, unsigned short& h, unsigned short& l) {
    __nv_bfloat16 bh = __float2bfloat16(v);
    float rem = v - __bfloat162float(bh);
    __nv_bfloat16 bl = __float2bfloat16(rem);
    h = __bfloat16_as_ushort(bh);
    l = __bfloat16_as_ushort(bl);
}

__device__ __forceinline__ uint32_t smem_u32(const void* p) {
    uint32_t a;
    asm("{ .reg .u64 t; cvta.to.shared.u64 t, %1; cvt.u32.u64 %0, t; }" : "=r"(a) : "l"(p));
    return a;
}

#define CP16(dst, src) \
    asm volatile("cp.async.cg.shared.global [%0], [%1], 16;" :: "r"(dst), "l"(src) : "memory")
#define CP_COMMIT() asm volatile("cp.async.commit_group;" ::: "memory")
#define CP_WAIT(n)  asm volatile("cp.async.wait_group %0;" :: "n"(n) : "memory")

__device__ __forceinline__ void mma16(float* c, const uint32_t* a, const uint32_t* b) {
    asm volatile(
        "mma.sync.aligned.m16n8k16.row.col.f32.bf16.bf16.f32 "
        "{%0,%1,%2,%3}, {%4,%5,%6,%7}, {%8,%9}, {%0,%1,%2,%3};"
        : "+f"(c[0]), "+f"(c[1]), "+f"(c[2]), "+f"(c[3])
        : "r"(a[0]), "r"(a[1]), "r"(a[2]), "r"(a[3]), "r"(b[0]), "r"(b[1]));
}

__device__ __forceinline__ void ldsm4(uint32_t* r, uint32_t addr) {
    asm volatile("ldmatrix.sync.aligned.m8n8.x4.shared.b16 {%0,%1,%2,%3}, [%4];"
        : "=r"(r[0]), "=r"(r[1]), "=r"(r[2]), "=r"(r[3]) : "r"(addr));
}
__device__ __forceinline__ void ldsm2(uint32_t* r, uint32_t addr) {
    asm volatile("ldmatrix.sync.aligned.m8n8.x2.shared.b16 {%0,%1}, [%2];"
        : "=r"(r[0]), "=r"(r[1]) : "r"(addr));
}

// ---------------- launch 0: router ----------------
__global__ void router_kernel(const float* __restrict__ x, const float* __restrict__ rw) {
    int gwarp = (blockIdx.x * blockDim.x + threadIdx.x) >> 5;
    int lane = threadIdx.x & 31;
    if (gwarp >= TT) return;
    const float* xr = x + (size_t)gwarp * DDIM;
    float acc[8] = {0.f,0.f,0.f,0.f,0.f,0.f,0.f,0.f};
    for (int d = lane; d < DDIM; d += 32) {
        float xv = xr[d];
        const float4* r4 = (const float4*)(rw + (size_t)d * EE);
        float4 a = r4[0], b = r4[1];
        acc[0] += xv * a.x; acc[1] += xv * a.y; acc[2] += xv * a.z; acc[3] += xv * a.w;
        acc[4] += xv * b.x; acc[5] += xv * b.y; acc[6] += xv * b.z; acc[7] += xv * b.w;
    }
    #pragma unroll
    for (int e = 0; e < 8; e++)
        #pragma unroll
        for (int s = 16; s > 0; s >>= 1)
            acc[e] += __shfl_xor_sync(0xffffffffu, acc[e], s);
    if (lane == 0) {
        int i0 = 0; float v0 = acc[0];
        #pragma unroll
        for (int e = 1; e < 8; e++) if (acc[e] > v0) { v0 = acc[e]; i0 = e; }
        int i1 = -1; float v1 = -3.4e38f;
        #pragma unroll
        for (int e = 0; e < 8; e++) if (e != i0 && acc[e] > v1) { v1 = acc[e]; i1 = e; }
        g_e0[gwarp] = i0; g_e1[gwarp] = i1;
        g_p0[gwarp] = 1.0f / (1.0f + __expf(-v0));
        g_p1[gwarp] = 1.0f / (1.0f + __expf(-v1));
    }
}

// ---------------- launch 1: deterministic compaction ----------------
__global__ void build_lists_kernel() {
    int e = blockIdx.x;
    int tid = threadIdx.x;
    int lane = tid & 31, wid = tid >> 5;
    __shared__ int wsum[8];
    __shared__ int base_s;
    if (tid == 0) base_s = 0;
    __syncthreads();
    for (int t0 = 0; t0 < TT; t0 += 256) {
        int t = t0 + tid;
        bool sel = false; float p = 0.f; bool first = false;
        if (g_e0[t] == e)      { sel = true; p = g_p0[t]; first = true; }
        else if (g_e1[t] == e) { sel = true; p = g_p1[t]; }
        unsigned m = __ballot_sync(0xffffffffu, sel);
        int rank = __popc(m & ((1u << lane) - 1));
        if (lane == 0) wsum[wid] = __popc(m);
        __syncthreads();
        int woff = 0;
        #pragma unroll
        for (int w = 0; w < 8; w++) if (w < wid) woff += wsum[w];
        if (sel) {
            int idx = base_s + woff + rank;
            g_ltok[e * TT + idx] = t;
            g_lp[e * TT + idx]   = p;
            if (first) g_sl0[t] = idx; else g_sl1[t] = idx;
        }
        __syncthreads();
        if (tid == 0) {
            int tot = 0;
            #pragma unroll
            for (int w = 0; w < 8; w++) tot += wsum[w];
            base_s += tot;
        }
        __syncthreads();
    }
    if (tid == 0) g_cnt[e] = base_s;
}

// ---------------- launch 2: all conversions + offsets ----------------
#define NB_SPLIT 8192
#define NB_GU    36864
#define NB_DN    18432
__global__ void conv_all(const float* __restrict__ x,
                         const float* __restrict__ guw,
                         const float* __restrict__ dw,
                         const float* __restrict__ sgw,
                         const float* __restrict__ suw,
                         const float* __restrict__ sdw) {
    __shared__ float tile[32][33];
    const int b = blockIdx.x;
    const int tid = threadIdx.x;

    if (b == 0 && tid == 0) {
        int o = 0;
        #pragma unroll
        for (int e = 0; e < EE; e++) { g_off[e] = o; o += g_cnt[e]; }
    }

    if (b < NB_SPLIT) {
        size_t i = ((size_t)b * 256 + tid) * 4;
        float4 v = *(const float4*)(x + i);
        ushort4 h, l;
        splitbf(v.x, h.x, l.x); splitbf(v.y, h.y, l.y);
        splitbf(v.z, h.z, l.z); splitbf(v.w, h.w, l.w);
        *(ushort4*)(g_xhi + i) = h;
        *(ushort4*)(g_xlo + i) = l;
        return;
    }
    const int tx = tid & 31, ty = tid >> 5;
    if (b < NB_SPLIT + NB_GU) {
        int bb = b - NB_SPLIT;
        int bx = bb & 63, by = (bb >> 6) & 63, e = bb >> 12;
        int n0 = bx * 32, k0 = by * 32;
        const float* src; int ld, nsrc0;
        if (e < 8)          { src = guw + (size_t)e * 2048 * 2048; ld = 2048; nsrc0 = n0; }
        else if (n0 < 1024) { src = sgw; ld = 1024; nsrc0 = n0; }
        else                { src = suw; ld = 1024; nsrc0 = n0 - 1024; }
        #pragma unroll
        for (int j = 0; j < 4; j++) {
            int k = k0 + ty + j * 8;
            tile[ty + j * 8][tx] = src[(size_t)k * ld + nsrc0 + tx];
        }
        __syncthreads();
        #pragma unroll
        for (int j = 0; j < 4; j++) {
            int n = n0 + ty + j * 8;
            float v = tile[tx][ty + j * 8];
            unsigned short h, l;
            splitbf(v, h, l);
            size_t di = ((size_t)e * 2048 + n) * 2048 + k0 + tx;
            g_bguh[di] = h; g_bgul[di] = l;
        }
        return;
    }
    {
        int bb = b - NB_SPLIT - NB_GU;
        int bx = bb & 63, by = (bb >> 6) & 31, e = bb >> 11;
        int n0 = bx * 32, k0 = by * 32;
        const float* src = (e < 8) ? (dw + (size_t)e * 1024 * 2048) : sdw;
        #pragma unroll
        for (int j = 0; j < 4; j++) {
            int k = k0 + ty + j * 8;
            tile[ty + j * 8][tx] = src[(size_t)k * 2048 + n0 + tx];
        }
        __syncthreads();
        #pragma unroll
        for (int j = 0; j < 4; j++) {
            int n = n0 + ty + j * 8;
            float v = tile[tx][ty + j * 8];
            unsigned short h, l;
            splitbf(v, h, l);
            size_t di = ((size_t)e * 2048 + n) * 1024 + k0 + tx;
            g_bdnh[di] = h; g_bdnl[di] = l;
        }
    }
}

// ---------------- mainloop: warp tile 64x64, 192 MMA/k-tile/warp ----------------
#define MAINLOOP_KTILE(base)                                                     \
    {                                                                            \
        const uint32_t Ah = (base) + aoff;                                       \
        const uint32_t Al = Ah + ARR_B;                                          \
        const uint32_t Bh = (base) + 2 * ARR_B + boff;                           \
        const uint32_t Bl = Bh + ARR_B;                                          \
        _Pragma("unroll")                                                        \
        for (int s = 0; s < 2; s++) {                                            \
            uint32_t bhf[8][2], blf[8][2];                                       \
            _Pragma("unroll")                                                    \
            for (int ni = 0; ni < 8; ni++) {                                     \
                ldsm2(bhf[ni], Bh + ni * (8 * ROW_B) + s * 32);                  \
                ldsm2(blf[ni], Bl + ni * (8 * ROW_B) + s * 32);                  \
            }                                                                    \
            _Pragma("unroll")                                                    \
            for (int mi = 0; mi < 4; mi++) {                                     \
                uint32_t ah[4], al[4];                                           \
                ldsm4(ah, Ah + mi * (16 * ROW_B) + s * 32);                      \
                ldsm4(al, Al + mi * (16 * ROW_B) + s * 32);                      \
                _Pragma("unroll")                                                \
                for (int ni = 0; ni < 8; ni++) {                                 \
                    mma16(acc[mi][ni], ah, bhf[ni]);                             \
                    mma16(acc[mi][ni], ah, blf[ni]);                             \
                    mma16(acc[mi][ni], al, bhf[ni]);                             \
                }                                                                \
            }                                                                    \
        }                                                                        \
    }

// ---------------- launch 3: fused gate_up GEMM + SiLU + bf16-split h ----------------
// CTA tile 128m x 128n (64 gate + 64 up cols, interleaved per 16). grid (16, 32, 9)
__global__ void __launch_bounds__(128, 2)
gemm_gu_fused()
{
    const int KD = 2048;
    extern __shared__ char smem[];
    const uint32_t sb = smem_u32(smem);
    const int tid = threadIdx.x;
    const int e = blockIdx.z;
    const int row0 = blockIdx.y * 128;
    const int col0g = blockIdx.x * 64;   // gate col base (up = 1024 + same)

    int M, soff;
    const float* lpp = nullptr;
    const int* ltok = nullptr;
    if (e < 8) { M = g_cnt[e]; soff = g_off[e]; ltok = g_ltok + e * TT; lpp = g_lp + e * TT; }
    else       { M = TT; soff = RTOT; }
    if (row0 >= M) return;

    // cp.async plan: 16 chunks/thread (A: 1024 chunks, B: 1024 chunks)
    const char* src[NCHUNK]; uint32_t dst[NCHUNK];
    #pragma unroll
    for (int i = 0; i < NCHUNK; i++) {
        int idx = tid + i * 128;
        const unsigned short* rowp;
        if (idx < 1024) {        // A side
            int arr = idx >> 9, ci = idx & 511;
            int r = ci >> 2, ch = ci & 3;
            int gr = row0 + r;
            size_t tok = (e < 8) ? (size_t)((gr < M) ? ltok[gr] : 0) : (size_t)gr;
            rowp = ((arr == 0) ? g_xhi : g_xlo) + tok * DDIM;
            src[i] = (const char*)rowp + ch * 16;
            dst[i] = sb + (uint32_t)(arr * ARR_B + r * ROW_B + ch * 16);
        } else {                 // B side: 128 rows = 4 groups of (16 gate + 16 up)
            int bi = idx - 1024;
            int arr = bi >> 9, ci = bi & 511;
            int r = ci >> 2, ch = ci & 3;
            int grp = r >> 5, w = r & 31;
            int ncol = (w < 16) ? (col0g + grp * 16 + w)
                                : (1024 + col0g + grp * 16 + (w - 16));
            rowp = ((arr == 0) ? g_bguh : g_bgul) + ((size_t)e * 2048 + ncol) * (size_t)KD;
            src[i] = (const char*)rowp + ch * 16;
            dst[i] = sb + (uint32_t)(2 * ARR_B + arr * ARR_B + r * ROW_B + ch * 16);
        }
    }

    const int lane = tid & 31;
    const int g = lane >> 2, t = lane & 3;
    const int wm = (tid >> 5) & 1, wn = (tid >> 5) >> 1;   // 2 x 2 warps

    const uint32_t aoff = (uint32_t)((wm * 64 + (lane & 7) + ((lane >> 3) & 1) * 8) * ROW_B
                                     + (lane >> 4) * 16);
    const uint32_t boff = (uint32_t)((wn * 64 + (lane & 7)) * ROW_B + ((lane >> 3) & 1) * 16);

    float acc[4][8][4];
    #pragma unroll
    for (int mi = 0; mi < 4; mi++)
        #pragma unroll
        for (int ni = 0; ni < 8; ni++)
            #pragma unroll
            for (int r = 0; r < 4; r++) acc[mi][ni][r] = 0.f;

    #pragma unroll
    for (int i = 0; i < NCHUNK; i++) { CP16(dst[i], src[i]); src[i] += 64; }
    CP_COMMIT();

    const int NK = KD / KT;
    for (int it = 0; it < NK; it++) {
        CP_WAIT(0);
        __syncthreads();
        if (it + 1 < NK) {
            uint32_t so = (uint32_t)(((it + 1) & 1) * STAGE_B);
            #pragma unroll
            for (int i = 0; i < NCHUNK; i++) { CP16(dst[i] + so, src[i]); src[i] += 64; }
            CP_COMMIT();
        }
        const uint32_t base = sb + (uint32_t)((it & 1) * STAGE_B);
        MAINLOOP_KTILE(base)
    }

    // fused epilogue: h = silu(p*gate) * (p*up), split bf16, store
    // gate acc at ni {0,1,4,5}; up at ni+2
    #pragma unroll
    for (int mi = 0; mi < 4; mi++) {
        int grb = row0 + wm * 64 + mi * 16 + g;
        #pragma unroll
        for (int pass = 0; pass < 2; pass++) {
            int gr = grb + pass * 8;
            if (gr < M) {
                float p = (e < 8) ? lpp[gr] : 1.f;
                size_t slot = (size_t)(soff + gr);
                #pragma unroll
                for (int pb = 0; pb < 2; pb++) {
                    #pragma unroll
                    for (int j = 0; j < 2; j++) {
                        int ni = pb * 4 + j;
                        float gv0 = p * acc[mi][ni][pass * 2 + 0];
                        float gv1 = p * acc[mi][ni][pass * 2 + 1];
                        float uv0 = p * acc[mi][ni + 2][pass * 2 + 0];
                        float uv1 = p * acc[mi][ni + 2][pass * 2 + 1];
                        float h0 = siluf(gv0) * uv0;
                        float h1 = siluf(gv1) * uv1;
                        unsigned short h0h, h0l, h1h, h1l;
                        splitbf(h0, h0h, h0l);
                        splitbf(h1, h1h, h1l);
                        int col = col0g + (2 * wn + pb) * 16 + j * 8 + 2 * t;
                        ushort2 hh; hh.x = h0h; hh.y = h1h;
                        ushort2 hl; hl.x = h0l; hl.y = h1l;
                        *(ushort2*)(g_rhh + slot * 1024 + col) = hh;
                        *(ushort2*)(g_rhl + slot * 1024 + col) = hl;
                    }
                }
            }
        }
    }
}

// ---------------- launch 4: down GEMM, plain slot stores. grid (16, 32, 9) ----------------
__global__ void __launch_bounds__(128, 2)
gemm_down()
{
    const int KD = 1024;
    extern __shared__ char smem[];
    const uint32_t sb = smem_u32(smem);
    const int tid = threadIdx.x;
    const int e = blockIdx.z;
    const int row0 = blockIdx.y * 128;
    const int col0 = blockIdx.x * 128;

    int M, soff;
    if (e < 8) { M = g_cnt[e]; soff = g_off[e]; } else { M = TT; soff = RTOT; }
    if (row0 >= M) return;

    const char* src[NCHUNK]; uint32_t dst[NCHUNK];
    #pragma unroll
    for (int i = 0; i < NCHUNK; i++) {
        int idx = tid + i * 128;
        const unsigned short* rowp;
        if (idx < 1024) {
            int arr = idx >> 9, ci = idx & 511;
            int r = ci >> 2, ch = ci & 3;
            int gr = row0 + r;
            size_t slot = (size_t)(soff + ((gr < M) ? gr : 0));
            rowp = ((arr == 0) ? g_rhh : g_rhl) + slot * 1024;
            src[i] = (const char*)rowp + ch * 16;
            dst[i] = sb + (uint32_t)(arr * ARR_B + r * ROW_B + ch * 16);
        } else {
            int bi = idx - 1024;
            int arr = bi >> 9, ci = bi & 511;
            int r = ci >> 2, ch = ci & 3;
            rowp = ((arr == 0) ? g_bdnh : g_bdnl) + ((size_t)e * 2048 + col0 + r) * (size_t)KD;
            src[i] = (const char*)rowp + ch * 16;
            dst[i] = sb + (uint32_t)(2 * ARR_B + arr * ARR_B + r * ROW_B + ch * 16);
        }
    }

    const int lane = tid & 31;
    const int g = lane >> 2, t = lane & 3;
    const int wm = (tid >> 5) & 1, wn = (tid >> 5) >> 1;

    const uint32_t aoff = (uint32_t)((wm * 64 + (lane & 7) + ((lane >> 3) & 1) * 8) * ROW_B
                                     + (lane >> 4) * 16);
    const uint32_t boff = (uint32_t)((wn * 64 + (lane & 7)) * ROW_B + ((lane >> 3) & 1) * 16);

    float acc[4][8][4];
    #pragma unroll
    for (int mi = 0; mi < 4; mi++)
        #pragma unroll
        for (int ni = 0; ni < 8; ni++)
            #pragma unroll
            for (int r = 0; r < 4; r++) acc[mi][ni][r] = 0.f;

    #pragma unroll
    for (int i = 0; i < NCHUNK; i++) { CP16(dst[i], src[i]); src[i] += 64; }
    CP_COMMIT();

    const int NK = KD / KT;
    for (int it = 0; it < NK; it++) {
        CP_WAIT(0);
        __syncthreads();
        if (it + 1 < NK) {
            uint32_t so = (uint32_t)(((it + 1) & 1) * STAGE_B);
            #pragma unroll
            for (int i = 0; i < NCHUNK; i++) { CP16(dst[i] + so, src[i]); src[i] += 64; }
            CP_COMMIT();
        }
        const uint32_t base = sb + (uint32_t)((it & 1) * STAGE_B);
        MAINLOOP_KTILE(base)
    }

    #pragma unroll
    for (int mi = 0; mi < 4; mi++) {
        int gr0 = row0 + wm * 64 + mi * 16 + g;
        int gr1 = gr0 + 8;
        bool v0 = gr0 < M, v1 = gr1 < M;
        float* d0 = g_do + (size_t)(soff + gr0) * 2048 + col0 + wn * 64;
        float* d1 = g_do + (size_t)(soff + gr1) * 2048 + col0 + wn * 64;
        #pragma unroll
        for (int ni = 0; ni < 8; ni++) {
            int cc = ni * 8 + 2 * t;
            if (v0) { float2 v; v.x = acc[mi][ni][0]; v.y = acc[mi][ni][1]; *(float2*)(d0 + cc) = v; }
            if (v1) { float2 v; v.x = acc[mi][ni][2]; v.y = acc[mi][ni][3]; *(float2*)(d1 + cc) = v; }
        }
    }
}

// ---------------- launch 5: combine ----------------
__global__ void combine_kernel(float* __restrict__ out) {
    int t = blockIdx.x;
    int c = threadIdx.x * 8;
    int s0 = g_off[g_e0[t]] + g_sl0[t];
    int s1 = g_off[g_e1[t]] + g_sl1[t];
    const float* pa = g_do + (size_t)(RTOT + t) * 2048 + c;
    const float* pb = g_do + (size_t)s0 * 2048 + c;
    const float* pc = g_do + (size_t)s1 * 2048 + c;
    float* po = out + (size_t)t * 2048 + c;
    #pragma unroll
    for (int j = 0; j < 2; j++) {
        float4 a = *(const float4*)(pa + j * 4);
        float4 b = *(const float4*)(pb + j * 4);
        float4 d = *(const float4*)(pc + j * 4);
        float4 o;
        o.x = a.x + b.x + d.x; o.y = a.y + b.y + d.y;
        o.z = a.z + b.z + d.z; o.w = a.w + b.w + d.w;
        *(float4*)(po + j * 4) = o;
    }
}

// ---------------- launch ----------------
extern "C" void kernel_launch(void* const* d_in, const int* in_sizes, int n_in,
                              void* d_out, int out_size) {
    const float* x   = (const float*)d_in[0];
    const float* rw  = (const float*)d_in[1];
    const float* guw = (const float*)d_in[2];
    const float* dw  = (const float*)d_in[3];
    const float* sgw = (const float*)d_in[4];
    const float* suw = (const float*)d_in[5];
    const float* sdw = (const float*)d_in[6];
    float* out = (float*)d_out;

    cudaFuncSetAttribute(gemm_gu_fused, cudaFuncAttributeMaxDynamicSharedMemorySize, SMEM_BYTES);
    cudaFuncSetAttribute(gemm_down,     cudaFuncAttributeMaxDynamicSharedMemorySize, SMEM_BYTES);

    router_kernel<<<TT / 8, 256>>>(x, rw);                                    // #0
    build_lists_kernel<<<EE, 256>>>();                                        // #1
    conv_all<<<NB_SPLIT + NB_GU + NB_DN, 256>>>(x, guw, dw, sgw, suw, sdw);   // #2
    gemm_gu_fused<<<dim3(16, 32, 9), 128, SMEM_BYTES>>>();                    // #3 (profiled)
    gemm_down<<<dim3(16, 32, 9), 128, SMEM_BYTES>>>();                        // #4
    combine_kernel<<<TT, 256>>>(out);                                         // #5
}